// round 16
// baseline (speedup 1.0000x reference)
#include <cuda_runtime.h>
#include <cstdint>

// AggregateLevels: FPN anchor generation + delta decode, 5 levels fused.
// B=16, IH=IW=1024. A = 261888 = 1023*256 (exact grid, no bounds checks).
// ILP across BATCHES: each thread owns one position p and 4 batches.
// Loads streaming (__ldcs); stores DEFAULT policy (let L2 buffer + batch
// writebacks into long write trains instead of evict-first interleaving).
// Output (float32): scores [B,A,2] @0 ; boxes [B,A,4] @B*A*2 ; anchors [B,A,4] @B*A*6.

#define B_SZ   16
#define A_TOT  261888
#define TPB    256
#define KB     4            // batches per thread

__constant__ int   c_off[5]   = {0, 196608, 245760, 258048, 261120};
__constant__ int   c_lghw[5]  = {16, 14, 12, 10, 8};
__constant__ int   c_lgw[5]   = {8, 7, 6, 5, 4};
__constant__ float c_scale[5] = {4.f, 8.f, 16.f, 32.f, 64.f};
__constant__ float c_half[5]  = {1.5f, 3.5f, 7.5f, 15.5f, 31.5f};
__constant__ float c_anch[5]  = {0.0625f, 0.125f, 0.25f, 0.5f, 1.0f}; // 2^(i-6)

struct Ptrs {
    const float* cs[5];
    const float* bp[5];
    const int*   ih;
    const int*   iw;
};

__global__ __launch_bounds__(TPB)
void aggregate_levels_kernel(Ptrs ptrs, float* __restrict__ out) {
    const int p  = blockIdx.x * TPB + threadIdx.x;   // < A_TOT always (1023*256)
    const int b0 = blockIdx.y * KB;

    // ---- decode ONCE per thread ----
    const int lv   = (p >= 196608) + (p >= 245760) + (p >= 258048) + (p >= 261120);
    const int q    = p - c_off[lv];
    const int lghw = c_lghw[lv];
    const int hw   = 1 << lghw;
    const int a    = q >> lghw;            // aspect 0..2
    const int rem  = q & (hw - 1);
    const int lgw  = c_lgw[lv];
    const int y    = rem >> lgw;
    const int x    = rem & ((1 << lgw) - 1);

    const float fih = (float)(*ptrs.ih);
    const float fiw = (float)(*ptrs.iw);

    const float s    = c_scale[lv];
    const float hc   = c_half[lv];
    const float an   = c_anch[lv];
    const float a_cy = s * (float)y + hc;
    const float a_cx = s * (float)x + hc;
    const float ha   = fih * an;
    const float wa   = fiw * an;
    const float a_h  = (a == 2) ? 2.0f * ha : ha;   // hs = {ha, ha, 2ha}
    const float a_w  = (a == 0) ? 2.0f * wa : wa;   // ws = {2wa, wa, wa}

    // ---- issue ALL 24 loads (4 batches x 6 planes) before any consumption ----
    const float* cs0 = ptrs.cs[lv] + (((b0 * 6  + a * 2) << lghw) + rem);
    const float* bp0 = ptrs.bp[lv] + (((b0 * 12 + a * 4) << lghw) + rem);
    const int cs_str = 6  << lghw;          // per-batch stride in cs
    const int bp_str = 12 << lghw;          // per-batch stride in bp

    float c0[KB], c1[KB], d0[KB], d1[KB], d2[KB], d3[KB];
    #pragma unroll
    for (int k = 0; k < KB; ++k) {
        const float* cs = cs0 + k * cs_str;
        const float* bp = bp0 + k * bp_str;
        c0[k] = __ldcs(cs);
        c1[k] = __ldcs(cs + hw);
        d0[k] = __ldcs(bp);
        d1[k] = __ldcs(bp + hw);
        d2[k] = __ldcs(bp + 2 * hw);
        d3[k] = __ldcs(bp + 3 * hw);
    }

    // ---- compute + store (default cache policy) ----
    float2* os = reinterpret_cast<float2*>(out);
    float4* ob = reinterpret_cast<float4*>(out + (size_t)B_SZ * A_TOT * 2);
    float4* oa = reinterpret_cast<float4*>(out + (size_t)B_SZ * A_TOT * 6);
    const float4 anc = make_float4(a_cy, a_cx, a_h, a_w);

    #pragma unroll
    for (int k = 0; k < KB; ++k) {
        const float cyc = a_cy + d0[k] * a_h;
        const float cxc = a_cx + d1[k] * a_w;
        const float hh  = a_h * __expf(d2[k]);
        const float ww  = a_w * __expf(d3[k]);

        const float y1 = fminf(fmaxf(cyc - 0.5f * hh, 0.0f), fih);
        const float x1 = fminf(fmaxf(cxc - 0.5f * ww, 0.0f), fiw);
        const float y2 = fminf(fmaxf(cyc + 0.5f * hh, 0.0f), fih);
        const float x2 = fminf(fmaxf(cxc + 0.5f * ww, 0.0f), fiw);

        const size_t idx = (size_t)(b0 + k) * A_TOT + p;
        os[idx] = make_float2(c0[k], c1[k]);
        ob[idx] = make_float4(y1, x1, y2, x2);
        oa[idx] = anc;
    }
}

extern "C" void kernel_launch(void* const* d_in, const int* in_sizes, int n_in,
                              void* d_out, int out_size) {
    (void)out_size;
    // Identify inputs by element count (robust to metadata ordering).
    Ptrs ptrs;
    ptrs.ih = nullptr; ptrs.iw = nullptr;
    for (int i = 0; i < n_in; ++i) {
        const long long sz = in_sizes[i];
        if (sz == 1) {
            if (!ptrs.ih) ptrs.ih = (const int*)d_in[i];
            else          ptrs.iw = (const int*)d_in[i];
            continue;
        }
        for (int l = 0; l < 5; ++l) {
            const long long hw = 65536LL >> (2 * l);
            if (sz == 16LL * 6 * hw)  ptrs.cs[l] = (const float*)d_in[i];
            if (sz == 16LL * 12 * hw) ptrs.bp[l] = (const float*)d_in[i];
        }
    }

    dim3 grid(A_TOT / TPB, B_SZ / KB);   // 1023 x 4
    aggregate_levels_kernel<<<grid, TPB>>>(ptrs, (float*)d_out);
}

// round 17
// speedup vs baseline: 1.0780x; 1.0780x over previous
#include <cuda_runtime.h>
#include <cstdint>

// AggregateLevels: FPN anchor generation + delta decode, 5 levels fused.
// B=16, IH=IW=1024. A = 261888.
// Pos-ILP 4 with WIDE blocks (512 thr): each block covers 2048 consecutive
// positions -> 8KB contiguous per input plane-stream per block (DRAM row
// locality), 16-32KB contiguous output streams. All loads issued before any
// consumption; all ld/st warp-contiguous.
// Output (float32): scores [B,A,2] @0 ; boxes [B,A,4] @B*A*2 ; anchors [B,A,4] @B*A*6.

#define B_SZ   16
#define A_TOT  261888
#define TPB    512
#define ILP    4
#define GRIDX  128          // 128 * 2048 = 262144 >= A_TOT

__constant__ int   c_off[5]   = {0, 196608, 245760, 258048, 261120};
__constant__ int   c_lghw[5]  = {16, 14, 12, 10, 8};
__constant__ int   c_lgw[5]   = {8, 7, 6, 5, 4};
__constant__ float c_scale[5] = {4.f, 8.f, 16.f, 32.f, 64.f};
__constant__ float c_half[5]  = {1.5f, 3.5f, 7.5f, 15.5f, 31.5f};
__constant__ float c_anch[5]  = {0.0625f, 0.125f, 0.25f, 0.5f, 1.0f}; // 2^(i-6)

struct Ptrs {
    const float* cs[5];
    const float* bp[5];
    const int*   ih;
    const int*   iw;
};

__global__ __launch_bounds__(TPB)
void aggregate_levels_kernel(Ptrs ptrs, float* __restrict__ out) {
    const int b  = blockIdx.y;
    const int p0 = blockIdx.x * (TPB * ILP) + threadIdx.x;

    const float fih = (float)(*ptrs.ih);
    const float fiw = (float)(*ptrs.iw);

    // ---- address + load phase: issue all 24 loads before any compute ----
    int   p[ILP], aa[ILP], yy[ILP], xx[ILP];
    bool  ok[ILP];
    float sc[ILP], hf[ILP], an[ILP];
    float c0[ILP], c1[ILP], d0[ILP], d1[ILP], d2[ILP], d3[ILP];

    #pragma unroll
    for (int k = 0; k < ILP; ++k) {
        p[k]  = p0 + k * TPB;
        ok[k] = (p[k] < A_TOT);
        const int pp = ok[k] ? p[k] : 0;
        const int lv = (pp >= 196608) + (pp >= 245760) + (pp >= 258048) + (pp >= 261120);
        const int q    = pp - c_off[lv];
        const int lghw = c_lghw[lv];
        const int hw   = 1 << lghw;
        aa[k]          = q >> lghw;           // aspect 0..2
        const int rem  = q & (hw - 1);
        const int lgw  = c_lgw[lv];
        yy[k] = rem >> lgw;
        xx[k] = rem & ((1 << lgw) - 1);
        sc[k] = c_scale[lv];
        hf[k] = c_half[lv];
        an[k] = c_anch[lv];

        const float* cs = ptrs.cs[lv] + (((b * 6  + aa[k] * 2) << lghw) + rem);
        const float* bp = ptrs.bp[lv] + (((b * 12 + aa[k] * 4) << lghw) + rem);
        c0[k] = __ldcs(cs);
        c1[k] = __ldcs(cs + hw);
        d0[k] = __ldcs(bp);
        d1[k] = __ldcs(bp + hw);
        d2[k] = __ldcs(bp + 2 * hw);
        d3[k] = __ldcs(bp + 3 * hw);
    }

    // ---- compute + store phase ----
    float2* os = reinterpret_cast<float2*>(out);
    float4* ob = reinterpret_cast<float4*>(out + (size_t)B_SZ * A_TOT * 2);
    float4* oa = reinterpret_cast<float4*>(out + (size_t)B_SZ * A_TOT * 6);

    #pragma unroll
    for (int k = 0; k < ILP; ++k) {
        if (!ok[k]) continue;
        const float a_cy = sc[k] * (float)yy[k] + hf[k];
        const float a_cx = sc[k] * (float)xx[k] + hf[k];
        const float ha   = fih * an[k];
        const float wa   = fiw * an[k];
        const float a_h  = (aa[k] == 2) ? 2.0f * ha : ha;   // hs = {ha, ha, 2ha}
        const float a_w  = (aa[k] == 0) ? 2.0f * wa : wa;   // ws = {2wa, wa, wa}

        const float cyc = a_cy + d0[k] * a_h;
        const float cxc = a_cx + d1[k] * a_w;
        const float hh  = a_h * __expf(d2[k]);
        const float ww  = a_w * __expf(d3[k]);

        const float y1 = fminf(fmaxf(cyc - 0.5f * hh, 0.0f), fih);
        const float x1 = fminf(fmaxf(cxc - 0.5f * ww, 0.0f), fiw);
        const float y2 = fminf(fmaxf(cyc + 0.5f * hh, 0.0f), fih);
        const float x2 = fminf(fmaxf(cxc + 0.5f * ww, 0.0f), fiw);

        const size_t idx = (size_t)b * A_TOT + p[k];
        __stcs(os + idx, make_float2(c0[k], c1[k]));
        __stcs(ob + idx, make_float4(y1, x1, y2, x2));
        __stcs(oa + idx, make_float4(a_cy, a_cx, a_h, a_w));
    }
}

extern "C" void kernel_launch(void* const* d_in, const int* in_sizes, int n_in,
                              void* d_out, int out_size) {
    (void)out_size;
    // Identify inputs by element count (robust to metadata ordering).
    Ptrs ptrs;
    ptrs.ih = nullptr; ptrs.iw = nullptr;
    for (int i = 0; i < n_in; ++i) {
        const long long sz = in_sizes[i];
        if (sz == 1) {
            if (!ptrs.ih) ptrs.ih = (const int*)d_in[i];
            else          ptrs.iw = (const int*)d_in[i];
            continue;
        }
        for (int l = 0; l < 5; ++l) {
            const long long hw = 65536LL >> (2 * l);
            if (sz == 16LL * 6 * hw)  ptrs.cs[l] = (const float*)d_in[i];
            if (sz == 16LL * 12 * hw) ptrs.bp[l] = (const float*)d_in[i];
        }
    }

    dim3 grid(GRIDX, B_SZ);
    aggregate_levels_kernel<<<grid, TPB>>>(ptrs, (float*)d_out);
}